// round 1
// baseline (speedup 1.0000x reference)
#include <cuda_runtime.h>
#include <math.h>

#define S_LEN  2048
#define DMODEL 2048
#define HEADS  16
#define DHEAD  128
#define MAXB   4

// ---------------------------------------------------------------------------
// Scratch (device globals: allocation-free per harness rules)
// Q,K,V laid out [B, H, S, DK]; X laid out [B, S, D]
// ---------------------------------------------------------------------------
__device__ float g_Q[(size_t)MAXB * HEADS * S_LEN * DHEAD];
__device__ float g_K[(size_t)MAXB * HEADS * S_LEN * DHEAD];
__device__ float g_V[(size_t)MAXB * HEADS * S_LEN * DHEAD];
__device__ float g_X[(size_t)MAXB * S_LEN * DMODEL];

// ---------------------------------------------------------------------------
// SGEMM (NT): C[M,N] = A[M,K] @ W[N,K]^T + bias[N]
// 128x128 tile, BK=8, 256 threads, 8x8 microtile per thread.
// splitHeads=1: write C to [B,H,S,DK] layout; else row-major [M,N].
// ---------------------------------------------------------------------------
__global__ __launch_bounds__(256) void gemm_nt_kernel(
    const float* __restrict__ A, const float* __restrict__ W,
    const float* __restrict__ bias, float* __restrict__ C,
    int M, int splitHeads)
{
    const int K = DMODEL;
    const int N = DMODEL;
    __shared__ float As[8][128];
    __shared__ float Ws[8][128];

    const int tid = threadIdx.x;
    const int bm  = blockIdx.y * 128;
    const int bn  = blockIdx.x * 128;
    const int ty  = tid >> 4;       // 0..15
    const int tx  = tid & 15;       // 0..15
    const int lr  = tid >> 1;       // load row 0..127
    const int lc  = (tid & 1) * 4;  // load col 0 or 4

    const float* Ap = A + (size_t)(bm + lr) * K + lc;
    const float* Wp = W + (size_t)(bn + lr) * K + lc;

    float acc[8][8];
#pragma unroll
    for (int i = 0; i < 8; i++)
#pragma unroll
        for (int j = 0; j < 8; j++) acc[i][j] = 0.f;

    for (int k0 = 0; k0 < K; k0 += 8) {
        float4 av = *(const float4*)(Ap + k0);
        float4 wv = *(const float4*)(Wp + k0);
        As[lc + 0][lr] = av.x; As[lc + 1][lr] = av.y;
        As[lc + 2][lr] = av.z; As[lc + 3][lr] = av.w;
        Ws[lc + 0][lr] = wv.x; Ws[lc + 1][lr] = wv.y;
        Ws[lc + 2][lr] = wv.z; Ws[lc + 3][lr] = wv.w;
        __syncthreads();
#pragma unroll
        for (int k = 0; k < 8; k++) {
            float a[8], b[8];
            *(float4*)(a)     = *(const float4*)(&As[k][ty * 8]);
            *(float4*)(a + 4) = *(const float4*)(&As[k][ty * 8 + 4]);
            *(float4*)(b)     = *(const float4*)(&Ws[k][tx * 8]);
            *(float4*)(b + 4) = *(const float4*)(&Ws[k][tx * 8 + 4]);
#pragma unroll
            for (int i = 0; i < 8; i++)
#pragma unroll
                for (int j = 0; j < 8; j++)
                    acc[i][j] = fmaf(a[i], b[j], acc[i][j]);
        }
        __syncthreads();
    }

    // Epilogue
#pragma unroll
    for (int i = 0; i < 8; i++) {
        const int m = bm + ty * 8 + i;
#pragma unroll
        for (int j = 0; j < 8; j++) {
            const int n = bn + tx * 8 + j;
            const float v = acc[i][j] + bias[n];
            if (splitHeads) {
                const int b = m / S_LEN, s = m % S_LEN;
                const int h = n / DHEAD, d = n % DHEAD;
                C[((((size_t)b * HEADS + h) * S_LEN) + s) * DHEAD + d] = v;
            } else {
                C[(size_t)m * N + n] = v;
            }
        }
    }
}

// ---------------------------------------------------------------------------
// Flash attention: per-(b,h,q-tile). BR=BC=64, DK=128, online softmax.
// Q,K stored K-major (transposed) in smem for conflict-free rank-1 updates.
// Output written to X in [B, S, D] layout (ready for output projection).
// ---------------------------------------------------------------------------
#define BR 64
#define BC 64

// dynamic smem layout (float offsets)
#define OFF_QST  0                        // [128][68]
#define OFF_KST  (OFF_QST + 128 * 68)     // [128][68]
#define OFF_VS   (OFF_KST + 128 * 68)     // [64][132]
#define OFF_PS   (OFF_VS  + 64 * 132)     // [64][68]
#define OFF_RED  (OFF_PS  + 64 * 68)      // [64][16]
#define OFF_MS   (OFF_RED + 64 * 16)      // [64]
#define OFF_LS   (OFF_MS  + 64)           // [64]
#define OFF_CORR (OFF_LS  + 64)           // [64]
#define SMEM_FLOATS (OFF_CORR + 64)
#define ATTN_SMEM_BYTES (SMEM_FLOATS * 4)

__global__ __launch_bounds__(256) void attn_kernel(
    const float* __restrict__ Q, const float* __restrict__ K,
    const float* __restrict__ V, float* __restrict__ X)
{
    extern __shared__ float sm[];
    float (*Qst)[68]  = (float(*)[68])(sm + OFF_QST);
    float (*Kst)[68]  = (float(*)[68])(sm + OFF_KST);
    float (*Vs)[132]  = (float(*)[132])(sm + OFF_VS);
    float (*Ps)[68]   = (float(*)[68])(sm + OFF_PS);
    float (*red)[16]  = (float(*)[16])(sm + OFF_RED);
    float* m_s    = sm + OFF_MS;
    float* l_s    = sm + OFF_LS;
    float* corr_s = sm + OFF_CORR;

    const int qt = blockIdx.x;
    const int h  = blockIdx.y;
    const int b  = blockIdx.z;
    const int tid = threadIdx.x;
    const int ty  = tid >> 4;    // 0..15 -> rows ty*4..+3
    const int tx  = tid & 15;    // 0..15 -> S cols tx*4..+3 / O cols tx*8..+7

    const float scale = 0.08838834764831845f;  // 1/sqrt(128)

    const float* Qp = Q + (((size_t)b * HEADS + h) * S_LEN + (size_t)qt * BR) * DHEAD;
    const float* Kb = K + ((size_t)b * HEADS + h) * S_LEN * DHEAD;
    const float* Vb = V + ((size_t)b * HEADS + h) * S_LEN * DHEAD;

    // Load Q tile transposed: Qst[k][r]
    for (int i = tid; i < BR * (DHEAD / 4); i += 256) {
        const int r  = i >> 5;          // /32 float4s per row
        const int c4 = (i & 31) * 4;
        float4 v = *(const float4*)(Qp + (size_t)r * DHEAD + c4);
        Qst[c4 + 0][r] = v.x; Qst[c4 + 1][r] = v.y;
        Qst[c4 + 2][r] = v.z; Qst[c4 + 3][r] = v.w;
    }
    if (tid < BR) { m_s[tid] = -INFINITY; l_s[tid] = 0.f; }

    float o[4][8];
#pragma unroll
    for (int i = 0; i < 4; i++)
#pragma unroll
        for (int j = 0; j < 8; j++) o[i][j] = 0.f;

    __syncthreads();

    for (int kt = 0; kt < S_LEN / BC; kt++) {
        const float* Kp = Kb + (size_t)kt * BC * DHEAD;
        const float* Vp = Vb + (size_t)kt * BC * DHEAD;
        // Load K transposed + V row-major
        for (int i = tid; i < BC * (DHEAD / 4); i += 256) {
            const int r  = i >> 5;
            const int c4 = (i & 31) * 4;
            float4 kv = *(const float4*)(Kp + (size_t)r * DHEAD + c4);
            Kst[c4 + 0][r] = kv.x; Kst[c4 + 1][r] = kv.y;
            Kst[c4 + 2][r] = kv.z; Kst[c4 + 3][r] = kv.w;
            *(float4*)(&Vs[r][c4]) = *(const float4*)(Vp + (size_t)r * DHEAD + c4);
        }
        __syncthreads();

        // S = scale * Q K^T  (4x4 microtile per thread)
        float s[4][4];
#pragma unroll
        for (int i = 0; i < 4; i++)
#pragma unroll
            for (int j = 0; j < 4; j++) s[i][j] = 0.f;
#pragma unroll 8
        for (int k = 0; k < DHEAD; k++) {
            float a[4], bb[4];
            *(float4*)a  = *(const float4*)(&Qst[k][ty * 4]);
            *(float4*)bb = *(const float4*)(&Kst[k][tx * 4]);
#pragma unroll
            for (int i = 0; i < 4; i++)
#pragma unroll
                for (int j = 0; j < 4; j++)
                    s[i][j] = fmaf(a[i], bb[j], s[i][j]);
        }
#pragma unroll
        for (int i = 0; i < 4; i++) {
            float mx = -INFINITY;
#pragma unroll
            for (int j = 0; j < 4; j++) {
                s[i][j] *= scale;
                mx = fmaxf(mx, s[i][j]);
            }
            red[ty * 4 + i][tx] = mx;
        }
        __syncthreads();

        if (tid < BR) {
            const float mo = m_s[tid];
            float mn = mo;
#pragma unroll
            for (int j = 0; j < 16; j++) mn = fmaxf(mn, red[tid][j]);
            m_s[tid] = mn;
            corr_s[tid] = __expf(mo - mn);   // exp(-inf)=0 on first tile
        }
        __syncthreads();

        // P = exp(S - m_new); partial row sums
#pragma unroll
        for (int i = 0; i < 4; i++) {
            const int r = ty * 4 + i;
            const float mn = m_s[r];
            float su = 0.f;
#pragma unroll
            for (int j = 0; j < 4; j++) {
                const float p = __expf(s[i][j] - mn);
                Ps[r][tx * 4 + j] = p;
                su += p;
            }
            red[r][tx] = su;
        }
        __syncthreads();

        if (tid < BR) {
            float su = 0.f;
#pragma unroll
            for (int j = 0; j < 16; j++) su += red[tid][j];
            l_s[tid] = l_s[tid] * corr_s[tid] + su;
        }

        // O = O*corr + P @ V
#pragma unroll
        for (int i = 0; i < 4; i++) {
            const float c = corr_s[ty * 4 + i];
#pragma unroll
            for (int j = 0; j < 8; j++) o[i][j] *= c;
        }
#pragma unroll 4
        for (int c = 0; c < BC; c++) {
            float p[4];
#pragma unroll
            for (int i = 0; i < 4; i++) p[i] = Ps[ty * 4 + i][c];
            float4 v0 = *(const float4*)(&Vs[c][tx * 8]);
            float4 v1 = *(const float4*)(&Vs[c][tx * 8 + 4]);
#pragma unroll
            for (int i = 0; i < 4; i++) {
                o[i][0] = fmaf(p[i], v0.x, o[i][0]);
                o[i][1] = fmaf(p[i], v0.y, o[i][1]);
                o[i][2] = fmaf(p[i], v0.z, o[i][2]);
                o[i][3] = fmaf(p[i], v0.w, o[i][3]);
                o[i][4] = fmaf(p[i], v1.x, o[i][4]);
                o[i][5] = fmaf(p[i], v1.y, o[i][5]);
                o[i][6] = fmaf(p[i], v1.z, o[i][6]);
                o[i][7] = fmaf(p[i], v1.w, o[i][7]);
            }
        }
        __syncthreads();   // protect Kst/Vs/red before next tile load
    }

    // Finalize: O / l, write X[B,S,D]
#pragma unroll
    for (int i = 0; i < 4; i++) {
        const int r = ty * 4 + i;
        const float inv = 1.f / l_s[r];
        float* Xp = X + ((size_t)b * S_LEN + (size_t)qt * BR + r) * DMODEL
                      + (size_t)h * DHEAD + tx * 8;
        float4 u0, u1;
        u0.x = o[i][0] * inv; u0.y = o[i][1] * inv;
        u0.z = o[i][2] * inv; u0.w = o[i][3] * inv;
        u1.x = o[i][4] * inv; u1.y = o[i][5] * inv;
        u1.z = o[i][6] * inv; u1.w = o[i][7] * inv;
        *(float4*)(Xp)     = u0;
        *(float4*)(Xp + 4) = u1;
    }
}

// ---------------------------------------------------------------------------
// Launch
// ---------------------------------------------------------------------------
extern "C" void kernel_launch(void* const* d_in, const int* in_sizes, int n_in,
                              void* d_out, int out_size)
{
    const float* query = (const float*)d_in[0];
    const float* key   = (const float*)d_in[1];
    const float* value = (const float*)d_in[2];
    const float* Wq    = (const float*)d_in[3];
    const float* bq    = (const float*)d_in[4];
    const float* Wk    = (const float*)d_in[5];
    const float* bk    = (const float*)d_in[6];
    const float* Wv    = (const float*)d_in[7];
    const float* bv    = (const float*)d_in[8];
    const float* Wo    = (const float*)d_in[9];
    const float* bo    = (const float*)d_in[10];

    const int B = in_sizes[0] / (S_LEN * DMODEL);
    const int M = B * S_LEN;

    float *Qd, *Kd, *Vd, *Xd;
    cudaGetSymbolAddress((void**)&Qd, g_Q);
    cudaGetSymbolAddress((void**)&Kd, g_K);
    cudaGetSymbolAddress((void**)&Vd, g_V);
    cudaGetSymbolAddress((void**)&Xd, g_X);

    cudaFuncSetAttribute(attn_kernel,
                         cudaFuncAttributeMaxDynamicSharedMemorySize,
                         ATTN_SMEM_BYTES);

    dim3 gGemm(DMODEL / 128, M / 128);

    gemm_nt_kernel<<<gGemm, 256>>>(query, Wq, bq, Qd, M, 1);
    gemm_nt_kernel<<<gGemm, 256>>>(key,   Wk, bk, Kd, M, 1);
    gemm_nt_kernel<<<gGemm, 256>>>(value, Wv, bv, Vd, M, 1);

    dim3 gAttn(S_LEN / BR, HEADS, B);
    attn_kernel<<<gAttn, 256, ATTN_SMEM_BYTES>>>(Qd, Kd, Vd, Xd);

    gemm_nt_kernel<<<gGemm, 256>>>(Xd, Wo, bo, (float*)d_out, M, 0);
}

// round 7
// speedup vs baseline: 1.7032x; 1.7032x over previous
#include <cuda_runtime.h>
#include <cuda_bf16.h>
#include <math.h>
#include <stdint.h>

#define S_LEN  2048
#define DMODEL 2048
#define HEADS  16
#define DHEAD  128
#define MAXB   4

// ---------------------------------------------------------------------------
// Scratch (device globals: allocation-free per harness rules)
// ---------------------------------------------------------------------------
__device__ float g_Q[(size_t)MAXB * HEADS * S_LEN * DHEAD];
__device__ float g_K[(size_t)MAXB * HEADS * S_LEN * DHEAD];
__device__ float g_V[(size_t)MAXB * HEADS * S_LEN * DHEAD];
__device__ float g_X[(size_t)MAXB * S_LEN * DMODEL];

// ---------------------------------------------------------------------------
// mma.sync m16n8k16 bf16 (family-common: compiles at compute_100)
// ---------------------------------------------------------------------------
__device__ __forceinline__ void mma16816(float* c, const uint32_t* a,
                                         const uint32_t* b) {
    asm volatile(
        "mma.sync.aligned.m16n8k16.row.col.f32.bf16.bf16.f32 "
        "{%0,%1,%2,%3}, {%4,%5,%6,%7}, {%8,%9}, {%0,%1,%2,%3};"
        : "+f"(c[0]), "+f"(c[1]), "+f"(c[2]), "+f"(c[3])
        : "r"(a[0]), "r"(a[1]), "r"(a[2]), "r"(a[3]), "r"(b[0]), "r"(b[1]));
}

__device__ __forceinline__ uint32_t pack_bf16(__nv_bfloat16 x, __nv_bfloat16 y) {
    __nv_bfloat162 v; v.x = x; v.y = y;
    return *(uint32_t*)&v;
}

// float4 -> 4 bf16 hi (uint2) + 4 bf16 lo (uint2)
__device__ __forceinline__ void cvt4(float4 v, uint2& hi, uint2& lo) {
    __nv_bfloat16 h0 = __float2bfloat16_rn(v.x), h1 = __float2bfloat16_rn(v.y);
    __nv_bfloat16 h2 = __float2bfloat16_rn(v.z), h3 = __float2bfloat16_rn(v.w);
    __nv_bfloat16 l0 = __float2bfloat16_rn(v.x - __bfloat162float(h0));
    __nv_bfloat16 l1 = __float2bfloat16_rn(v.y - __bfloat162float(h1));
    __nv_bfloat16 l2 = __float2bfloat16_rn(v.z - __bfloat162float(h2));
    __nv_bfloat16 l3 = __float2bfloat16_rn(v.w - __bfloat162float(h3));
    hi.x = pack_bf16(h0, h1); hi.y = pack_bf16(h2, h3);
    lo.x = pack_bf16(l0, l1); lo.y = pack_bf16(l2, l3);
}

// ---------------------------------------------------------------------------
// GEMM (NT): C[M,N] = A[M,K] @ W[N,K]^T + bias[N], 3-pass bf16 emulation.
// CTA 128x128, BK=32, 256 threads, warps 2(M)x4(N) -> warp tile 64x32.
// Smem: per stage 4 arrays (A_hi, A_lo, W_hi, W_lo), 128 rows x 40 bf16
// (32 data + 8 pad; 40*2B=80B row stride -> conflict-free fragment LDS).
// Double-buffered: 2 * 4 * 128*40*2 = 81920 B.
// ---------------------------------------------------------------------------
#define GSTRIDE     40
#define GARR        (128 * GSTRIDE)        // elems per array = 5120
#define GSTAGE      (4 * GARR)             // elems per stage = 20480
#define GEMM_SMEM_BYTES (2 * GSTAGE * 2)   // 81920 bytes
#define NKB (DMODEL / 32)                  // 64 K-blocks

__global__ __launch_bounds__(256, 1) void gemm_mma(
    const float* __restrict__ A, const float* __restrict__ W,
    const float* __restrict__ bias, float* __restrict__ C, int splitHeads)
{
    extern __shared__ __nv_bfloat16 s[];

    const int tid  = threadIdx.x;
    const int warp = tid >> 5, lane = tid & 31;
    const int g = lane >> 2, t = lane & 3;
    const int wm = (warp >> 2) * 64;    // 0 / 64
    const int wn = (warp & 3) * 32;     // 0 / 32 / 64 / 96
    const int bm = blockIdx.y * 128;
    const int bn = blockIdx.x * 128;

    // loader: iteration it covers row = it*32 + (tid>>3), kslot = tid&7
    const int lrow = tid >> 3, lks = tid & 7;

    float acc[4][4][4];
#pragma unroll
    for (int i = 0; i < 4; i++)
#pragma unroll
        for (int j = 0; j < 4; j++)
#pragma unroll
            for (int k = 0; k < 4; k++) acc[i][j][k] = 0.f;

    float4 pa[4], pw[4];

    // ---- prologue: stage 0 ----
#pragma unroll
    for (int it = 0; it < 4; it++) {
        const int r = it * 32 + lrow;
        pa[it] = *(const float4*)(A + (size_t)(bm + r) * DMODEL + lks * 4);
        pw[it] = *(const float4*)(W + (size_t)(bn + r) * DMODEL + lks * 4);
    }
#pragma unroll
    for (int it = 0; it < 4; it++) {
        const int r = it * 32 + lrow;
        const int off = r * GSTRIDE + lks * 4;
        uint2 hi, lo;
        cvt4(pa[it], hi, lo);
        *(uint2*)(s + off)            = hi;
        *(uint2*)(s + GARR + off)     = lo;
        cvt4(pw[it], hi, lo);
        *(uint2*)(s + 2 * GARR + off) = hi;
        *(uint2*)(s + 3 * GARR + off) = lo;
    }
    __syncthreads();

    for (int kb = 0; kb < NKB; kb++) {
        const int base = (kb & 1) * GSTAGE;

        // prefetch next K-block into registers
        if (kb + 1 < NKB) {
#pragma unroll
            for (int it = 0; it < 4; it++) {
                const int r = it * 32 + lrow;
                const size_t ko = (size_t)(kb + 1) * 32 + lks * 4;
                pa[it] = *(const float4*)(A + (size_t)(bm + r) * DMODEL + ko);
                pw[it] = *(const float4*)(W + (size_t)(bn + r) * DMODEL + ko);
            }
        }

        // compute: two k16 steps
#pragma unroll
        for (int k16 = 0; k16 < 32; k16 += 16) {
            const int c = k16 + t * 2;
            uint32_t ah[4][4], al[4][4];
#pragma unroll
            for (int mi = 0; mi < 4; mi++) {
                const int r0 = wm + mi * 16 + g;
                const int o0 = base + r0 * GSTRIDE + c;
                const int o1 = o0 + 8 * GSTRIDE;
                ah[mi][0] = *(const uint32_t*)(s + o0);
                ah[mi][1] = *(const uint32_t*)(s + o1);
                ah[mi][2] = *(const uint32_t*)(s + o0 + 8);
                ah[mi][3] = *(const uint32_t*)(s + o1 + 8);
                al[mi][0] = *(const uint32_t*)(s + GARR + o0);
                al[mi][1] = *(const uint32_t*)(s + GARR + o1);
                al[mi][2] = *(const uint32_t*)(s + GARR + o0 + 8);
                al[mi][3] = *(const uint32_t*)(s + GARR + o1 + 8);
            }
            uint32_t bh[4][2], bl[4][2];
#pragma unroll
            for (int ni = 0; ni < 4; ni++) {
                const int rn = wn + ni * 8 + g;
                const int o  = base + 2 * GARR + rn * GSTRIDE + c;
                bh[ni][0] = *(const uint32_t*)(s + o);
                bh[ni][1] = *(const uint32_t*)(s + o + 8);
                bl[ni][0] = *(const uint32_t*)(s + GARR + o);
                bl[ni][1] = *(const uint32_t*)(s + GARR + o + 8);
            }
#pragma unroll
            for (int mi = 0; mi < 4; mi++)
#pragma unroll
                for (int ni = 0; ni < 4; ni++) {
                    mma16816(acc[mi][ni], ah[mi], bh[ni]);
                    mma16816(acc[mi][ni], ah[mi], bl[ni]);
                    mma16816(acc[mi][ni], al[mi], bh[ni]);
                }
        }

        if (kb + 1 < NKB) {
            const int nbase = ((kb + 1) & 1) * GSTAGE;
#pragma unroll
            for (int it = 0; it < 4; it++) {
                const int r = it * 32 + lrow;
                const int off = nbase + r * GSTRIDE + lks * 4;
                uint2 hi, lo;
                cvt4(pa[it], hi, lo);
                *(uint2*)(s + off)            = hi;
                *(uint2*)(s + GARR + off)     = lo;
                cvt4(pw[it], hi, lo);
                *(uint2*)(s + 2 * GARR + off) = hi;
                *(uint2*)(s + 3 * GARR + off) = lo;
            }
            __syncthreads();
        }
    }

    // ---- epilogue ----
#pragma unroll
    for (int mi = 0; mi < 4; mi++) {
#pragma unroll
        for (int ni = 0; ni < 4; ni++) {
            const int col = bn + wn + ni * 8 + t * 2;
            const float b0 = bias[col], b1 = bias[col + 1];
#pragma unroll
            for (int h = 0; h < 2; h++) {
                const int m = bm + wm + mi * 16 + g + h * 8;
                float2 v;
                v.x = acc[mi][ni][h * 2 + 0] + b0;
                v.y = acc[mi][ni][h * 2 + 1] + b1;
                if (splitHeads) {
                    const int bb = m >> 11, ss = m & 2047;
                    const int hh = col >> 7, dd = col & 127;
                    *(float2*)(C + ((((size_t)bb * HEADS + hh) * S_LEN) + ss) * DHEAD + dd) = v;
                } else {
                    *(float2*)(C + (size_t)m * DMODEL + col) = v;
                }
            }
        }
    }
}

// ---------------------------------------------------------------------------
// Flash attention (known-good from R1): BR=BC=64, DK=128, fp32 SIMT.
// ---------------------------------------------------------------------------
#define BR 64
#define BC 64

#define OFF_QST  0
#define OFF_KST  (OFF_QST + 128 * 68)
#define OFF_VS   (OFF_KST + 128 * 68)
#define OFF_PS   (OFF_VS  + 64 * 132)
#define OFF_RED  (OFF_PS  + 64 * 68)
#define OFF_MS   (OFF_RED + 64 * 16)
#define OFF_LS   (OFF_MS  + 64)
#define OFF_CORR (OFF_LS  + 64)
#define SMEM_FLOATS (OFF_CORR + 64)
#define ATTN_SMEM_BYTES (SMEM_FLOATS * 4)

__global__ __launch_bounds__(256) void attn_kernel(
    const float* __restrict__ Q, const float* __restrict__ K,
    const float* __restrict__ V, float* __restrict__ X)
{
    extern __shared__ float smf[];
    float (*Qst)[68]  = (float(*)[68])(smf + OFF_QST);
    float (*Kst)[68]  = (float(*)[68])(smf + OFF_KST);
    float (*Vs)[132]  = (float(*)[132])(smf + OFF_VS);
    float (*Ps)[68]   = (float(*)[68])(smf + OFF_PS);
    float (*red)[16]  = (float(*)[16])(smf + OFF_RED);
    float* m_s    = smf + OFF_MS;
    float* l_s    = smf + OFF_LS;
    float* corr_s = smf + OFF_CORR;

    const int qt = blockIdx.x;
    const int h  = blockIdx.y;
    const int b  = blockIdx.z;
    const int tid = threadIdx.x;
    const int ty  = tid >> 4;
    const int tx  = tid & 15;

    const float scale = 0.08838834764831845f;

    const float* Qp = Q + (((size_t)b * HEADS + h) * S_LEN + (size_t)qt * BR) * DHEAD;
    const float* Kb = K + ((size_t)b * HEADS + h) * S_LEN * DHEAD;
    const float* Vb = V + ((size_t)b * HEADS + h) * S_LEN * DHEAD;

    for (int i = tid; i < BR * (DHEAD / 4); i += 256) {
        const int r  = i >> 5;
        const int c4 = (i & 31) * 4;
        float4 v = *(const float4*)(Qp + (size_t)r * DHEAD + c4);
        Qst[c4 + 0][r] = v.x; Qst[c4 + 1][r] = v.y;
        Qst[c4 + 2][r] = v.z; Qst[c4 + 3][r] = v.w;
    }
    if (tid < BR) { m_s[tid] = -INFINITY; l_s[tid] = 0.f; }

    float o[4][8];
#pragma unroll
    for (int i = 0; i < 4; i++)
#pragma unroll
        for (int j = 0; j < 8; j++) o[i][j] = 0.f;

    __syncthreads();

    for (int kt = 0; kt < S_LEN / BC; kt++) {
        const float* Kp = Kb + (size_t)kt * BC * DHEAD;
        const float* Vp = Vb + (size_t)kt * BC * DHEAD;
        for (int i = tid; i < BC * (DHEAD / 4); i += 256) {
            const int r  = i >> 5;
            const int c4 = (i & 31) * 4;
            float4 kv = *(const float4*)(Kp + (size_t)r * DHEAD + c4);
            Kst[c4 + 0][r] = kv.x; Kst[c4 + 1][r] = kv.y;
            Kst[c4 + 2][r] = kv.z; Kst[c4 + 3][r] = kv.w;
            *(float4*)(&Vs[r][c4]) = *(const float4*)(Vp + (size_t)r * DHEAD + c4);
        }
        __syncthreads();

        float sarr[4][4];
#pragma unroll
        for (int i = 0; i < 4; i++)
#pragma unroll
            for (int j = 0; j < 4; j++) sarr[i][j] = 0.f;
#pragma unroll 8
        for (int k = 0; k < DHEAD; k++) {
            float a[4], bb[4];
            *(float4*)a  = *(const float4*)(&Qst[k][ty * 4]);
            *(float4*)bb = *(const float4*)(&Kst[k][tx * 4]);
#pragma unroll
            for (int i = 0; i < 4; i++)
#pragma unroll
                for (int j = 0; j < 4; j++)
                    sarr[i][j] = fmaf(a[i], bb[j], sarr[i][j]);
        }
#pragma unroll
        for (int i = 0; i < 4; i++) {
            float mx = -INFINITY;
#pragma unroll
            for (int j = 0; j < 4; j++) {
                sarr[i][j] *= scale;
                mx = fmaxf(mx, sarr[i][j]);
            }
            red[ty * 4 + i][tx] = mx;
        }
        __syncthreads();

        if (tid < BR) {
            const float mo = m_s[tid];
            float mn = mo;
#pragma unroll
            for (int j = 0; j < 16; j++) mn = fmaxf(mn, red[tid][j]);
            m_s[tid] = mn;
            corr_s[tid] = __expf(mo - mn);
        }
        __syncthreads();

#pragma unroll
        for (int i = 0; i < 4; i++) {
            const int rr = ty * 4 + i;
            const float mn = m_s[rr];
            float su = 0.f;
#pragma unroll
            for (int j = 0; j < 4; j++) {
                const float p = __expf(sarr[i][j] - mn);
                Ps[rr][tx * 4 + j] = p;
                su += p;
            }
            red[rr][tx] = su;
        }
        __syncthreads();

        if (tid < BR) {
            float su = 0.f;
#pragma unroll
            for (int j = 0; j < 16; j++) su += red[tid][j];
            l_s[tid] = l_s[tid] * corr_s[tid] + su;
        }

#pragma unroll
        for (int i = 0; i < 4; i++) {
            const float cc = corr_s[ty * 4 + i];
#pragma unroll
            for (int j = 0; j < 8; j++) o[i][j] *= cc;
        }
#pragma unroll 4
        for (int c = 0; c < BC; c++) {
            float p[4];
#pragma unroll
            for (int i = 0; i < 4; i++) p[i] = Ps[ty * 4 + i][c];
            float4 v0 = *(const float4*)(&Vs[c][tx * 8]);
            float4 v1 = *(const float4*)(&Vs[c][tx * 8 + 4]);
#pragma unroll
            for (int i = 0; i < 4; i++) {
                o[i][0] = fmaf(p[i], v0.x, o[i][0]);
                o[i][1] = fmaf(p[i], v0.y, o[i][1]);
                o[i][2] = fmaf(p[i], v0.z, o[i][2]);
                o[i][3] = fmaf(p[i], v0.w, o[i][3]);
                o[i][4] = fmaf(p[i], v1.x, o[i][4]);
                o[i][5] = fmaf(p[i], v1.y, o[i][5]);
                o[i][6] = fmaf(p[i], v1.z, o[i][6]);
                o[i][7] = fmaf(p[i], v1.w, o[i][7]);
            }
        }
        __syncthreads();
    }

#pragma unroll
    for (int i = 0; i < 4; i++) {
        const int rr = ty * 4 + i;
        const float inv = 1.f / l_s[rr];
        float* Xp = X + ((size_t)b * S_LEN + (size_t)qt * BR + rr) * DMODEL
                      + (size_t)h * DHEAD + tx * 8;
        float4 u0, u1;
        u0.x = o[i][0] * inv; u0.y = o[i][1] * inv;
        u0.z = o[i][2] * inv; u0.w = o[i][3] * inv;
        u1.x = o[i][4] * inv; u1.y = o[i][5] * inv;
        u1.z = o[i][6] * inv; u1.w = o[i][7] * inv;
        *(float4*)(Xp)     = u0;
        *(float4*)(Xp + 4) = u1;
    }
}

// ---------------------------------------------------------------------------
// Launch
// ---------------------------------------------------------------------------
extern "C" void kernel_launch(void* const* d_in, const int* in_sizes, int n_in,
                              void* d_out, int out_size)
{
    const float* query = (const float*)d_in[0];
    const float* key   = (const float*)d_in[1];
    const float* value = (const float*)d_in[2];
    const float* Wq    = (const float*)d_in[3];
    const float* bq    = (const float*)d_in[4];
    const float* Wk    = (const float*)d_in[5];
    const float* bk    = (const float*)d_in[6];
    const float* Wv    = (const float*)d_in[7];
    const float* bv    = (const float*)d_in[8];
    const float* Wo    = (const float*)d_in[9];
    const float* bo    = (const float*)d_in[10];

    const int B = in_sizes[0] / (S_LEN * DMODEL);
    const int M = B * S_LEN;

    float *Qd, *Kd, *Vd, *Xd;
    cudaGetSymbolAddress((void**)&Qd, g_Q);
    cudaGetSymbolAddress((void**)&Kd, g_K);
    cudaGetSymbolAddress((void**)&Vd, g_V);
    cudaGetSymbolAddress((void**)&Xd, g_X);

    cudaFuncSetAttribute(gemm_mma,
                         cudaFuncAttributeMaxDynamicSharedMemorySize,
                         GEMM_SMEM_BYTES);
    cudaFuncSetAttribute(attn_kernel,
                         cudaFuncAttributeMaxDynamicSharedMemorySize,
                         ATTN_SMEM_BYTES);

    dim3 gGemm(DMODEL / 128, M / 128);

    gemm_mma<<<gGemm, 256, GEMM_SMEM_BYTES>>>(query, Wq, bq, Qd, 1);
    gemm_mma<<<gGemm, 256, GEMM_SMEM_BYTES>>>(key,   Wk, bk, Kd, 1);
    gemm_mma<<<gGemm, 256, GEMM_SMEM_BYTES>>>(value, Wv, bv, Vd, 1);

    dim3 gAttn(S_LEN / BR, HEADS, B);
    attn_kernel<<<gAttn, 256, ATTN_SMEM_BYTES>>>(Qd, Kd, Vd, Xd);

    gemm_mma<<<gGemm, 256, GEMM_SMEM_BYTES>>>(Xd, Wo, bo, (float*)d_out, 0);
}